// round 5
// baseline (speedup 1.0000x reference)
#include <cuda_runtime.h>
#include <cuda_bf16.h>
#include <cstddef>
#include <cstdint>

typedef unsigned long long ull;

// ---------------- problem constants ----------------
constexpr int Bc  = 256;
constexpr int Tc  = 512;
constexpr int Ic  = 64;
constexpr int Hc  = 512;
constexpr int Gc  = 4 * Hc;      // 2048
constexpr int HOR = 30;
constexpr int NQc = 3;
constexpr int NBLK = 128;        // persistent grid size (<= 148 SMs -> co-resident)

// ---------------- device scratch (__device__ globals: allocation-free) ----------------
__device__ float g_pre[(size_t)Bc * Tc * Gc];     // input projections (B*T, G), row m = b*Tc+t
__device__ float g_hs0[(size_t)Bc * Tc * Hc];     // layer-0 hidden history (B,T,H)
__device__ float g_encout[(size_t)Bc * Tc * Hc];  // layer-1 hidden history (B,T,H)
__device__ float g_encproj[(size_t)Bc * Tc * Hc]; // enc_out @ attn_W^T (B,T,H)

__device__ float g_Wih0p[Gc * Ic];
__device__ float g_Whh0p[Gc * Hc];
__device__ float g_Wih1p[Gc * Hc];
__device__ float g_Whh1p[Gc * Hc];
__device__ float g_dwrestp[Gc * Hc];
__device__ float g_dWhh0p[Gc * Hc];
__device__ float g_dWih1p[Gc * Hc];
__device__ float g_dWhh1p[Gc * Hc];
__device__ float g_dwcol0p[Gc];
__device__ float g_bE0p[Gc];
__device__ float g_bE1p[Gc];
__device__ float g_bD0p[Gc];
__device__ float g_bD1p[Gc];

__device__ float g_zero[Bc * Hc];
__device__ float g_c0[Bc * Hc];
__device__ float g_c1[Bc * Hc];
__device__ float g_hd0[Bc * Hc];
__device__ float g_hd1[Bc * Hc];
__device__ float g_cd0[Bc * Hc];
__device__ float g_cd1[Bc * Hc];
__device__ float g_cdump[Bc * Hc];
__device__ float g_h0tmp[Bc * Hc];
__device__ float g_ctx[Bc * Hc];
__device__ float g_decproj[Bc * Hc];
__device__ float g_energy[Bc * Tc];
__device__ float g_dinp[Bc];

// ---------------- grid barrier (monotonic release counter) ----------------
__device__ unsigned g_arrive = 0;
__device__ unsigned g_release = 0;

__device__ __forceinline__ void grid_sync() {
    __syncthreads();
    if (threadIdx.x == 0) {
        __threadfence();
        unsigned prev = *((volatile unsigned*)&g_release);
        unsigned a = atomicAdd(&g_arrive, 1u);
        if (a == gridDim.x - 1u) {
            atomicExch(&g_arrive, 0u);
            __threadfence();
            atomicExch(&g_release, prev + 1u);
        } else {
            while (*((volatile unsigned*)&g_release) == prev) __nanosleep(64);
        }
        __threadfence();
    }
    __syncthreads();
}

// ---------------- math helpers ----------------
__device__ __forceinline__ float sigf(float x) {
    return __fdividef(1.0f, 1.0f + __expf(-x));
}
__device__ __forceinline__ float tanhfast(float x) {
    return 1.0f - __fdividef(2.0f, __expf(2.0f * x) + 1.0f);
}
__device__ __forceinline__ ull pack2(float lo, float hi) {
    ull r; asm("mov.b64 %0, {%1, %2};" : "=l"(r) : "f"(lo), "f"(hi)); return r;
}
__device__ __forceinline__ float2 unpack2(ull v) {
    float2 f; asm("mov.b64 {%0, %1}, %2;" : "=f"(f.x), "=f"(f.y) : "l"(v)); return f;
}
__device__ __forceinline__ void fma2(ull& d, ull a, ull b) {
    asm("fma.rn.f32x2 %0, %1, %2, %0;" : "+l"(d) : "l"(a), "l"(b));
}

// ---------------- prep: weight permutation (gp = jh*4+q), biases, zeros, dinp ----------------
__global__ void prep_kernel(const float* __restrict__ x,
    const float* __restrict__ eWih0, const float* __restrict__ eWhh0,
    const float* __restrict__ ebih0, const float* __restrict__ ebhh0,
    const float* __restrict__ eWih1, const float* __restrict__ eWhh1,
    const float* __restrict__ ebih1, const float* __restrict__ ebhh1,
    const float* __restrict__ dWih0, const float* __restrict__ dWhh0,
    const float* __restrict__ dbih0, const float* __restrict__ dbhh0,
    const float* __restrict__ dWih1, const float* __restrict__ dWhh1,
    const float* __restrict__ dbih1, const float* __restrict__ dbhh1)
{
    int idx = blockIdx.x * 256 + threadIdx.x;          // covers Gc*Hc = 1,048,576
    if (idx < Gc * Hc) {
        int gp = idx / Hc;
        int k  = idx - gp * Hc;
        int g  = (gp & 3) * Hc + (gp >> 2);            // original gate row
        size_t src = (size_t)g * Hc + k;
        g_Whh0p[idx]  = eWhh0[src];
        g_Wih1p[idx]  = eWih1[src];
        g_Whh1p[idx]  = eWhh1[src];
        g_dWhh0p[idx] = dWhh0[src];
        g_dWih1p[idx] = dWih1[src];
        g_dWhh1p[idx] = dWhh1[src];
        g_dwrestp[idx] = dWih0[(size_t)g * (Hc + 1) + 1 + k];
        if (k < Ic) g_Wih0p[gp * Ic + k] = eWih0[(size_t)g * Ic + k];
        if (k == 0) {
            g_dwcol0p[gp] = dWih0[(size_t)g * (Hc + 1)];
            g_bE0p[gp] = ebih0[g] + ebhh0[g];
            g_bE1p[gp] = ebih1[g] + ebhh1[g];
            g_bD0p[gp] = dbih0[g] + dbhh0[g];
            g_bD1p[gp] = dbih1[g] + dbhh1[g];
        }
    }
    if (idx < Bc * Hc) { g_zero[idx] = 0.f; g_c0[idx] = 0.f; g_c1[idx] = 0.f; }
    if (idx < Bc) g_dinp[idx] = x[(size_t)idx * Tc * Ic + (size_t)(Tc - 1) * Ic];
}

// ---------------- shared GEMM tile core ----------------
// Computes a 64(M) x 64(N) tile of C += A(M,K) * W(N,K)^T, 256 threads,
// thread tile 4x4, columns accumulated as packed f32x2 pairs.
__device__ __forceinline__ void gemm_tile(
    const float* __restrict__ A, long lda,
    const float* __restrict__ W, long ldw, int K,
    ull (&acc)[4][2],
    float (&As)[32][72], float (&Bs)[32][72],
    long m0, int n0, int tid)
{
    const int lk = tid & 7, lm = tid >> 3;
    const float* ap = A + (m0 + lm) * lda + lk * 4;
    const float* wp = W + (long)(n0 + lm) * ldw + lk * 4;
    const int tm = tid >> 4, tn = tid & 15;

    for (int k0 = 0; k0 < K; k0 += 32) {
        float4 a0 = *(const float4*)(ap + k0);
        float4 a1 = *(const float4*)(ap + (long)32 * lda + k0);
        float4 w0 = *(const float4*)(wp + k0);
        float4 w1 = *(const float4*)(wp + (long)32 * ldw + k0);
        __syncthreads();   // previous tile fully consumed before overwrite
        As[lk*4+0][lm] = a0.x; As[lk*4+1][lm] = a0.y; As[lk*4+2][lm] = a0.z; As[lk*4+3][lm] = a0.w;
        As[lk*4+0][lm+32] = a1.x; As[lk*4+1][lm+32] = a1.y; As[lk*4+2][lm+32] = a1.z; As[lk*4+3][lm+32] = a1.w;
        Bs[lk*4+0][lm] = w0.x; Bs[lk*4+1][lm] = w0.y; Bs[lk*4+2][lm] = w0.z; Bs[lk*4+3][lm] = w0.w;
        Bs[lk*4+0][lm+32] = w1.x; Bs[lk*4+1][lm+32] = w1.y; Bs[lk*4+2][lm+32] = w1.z; Bs[lk*4+3][lm+32] = w1.w;
        __syncthreads();
#pragma unroll
        for (int k = 0; k < 32; ++k) {
            float4 av = *(const float4*)&As[k][tm * 4];
            float4 bv = *(const float4*)&Bs[k][tn * 4];
            ull bl = pack2(bv.x, bv.y);
            ull bh = pack2(bv.z, bv.w);
            ull aa;
            aa = pack2(av.x, av.x); fma2(acc[0][0], aa, bl); fma2(acc[0][1], aa, bh);
            aa = pack2(av.y, av.y); fma2(acc[1][0], aa, bl); fma2(acc[1][1], aa, bh);
            aa = pack2(av.z, av.z); fma2(acc[2][0], aa, bl); fma2(acc[2][1], aa, bh);
            aa = pack2(av.w, av.w); fma2(acc[3][0], aa, bl); fma2(acc[3][1], aa, bh);
        }
    }
}

// ---------------- LSTM cell epilogue ----------------
template <bool HASP, bool HASSCAL>
__device__ __forceinline__ void cell_epilogue(
    ull (&acc)[4][2], int m0, int n0, int tid,
    const float* __restrict__ P, long ldp,
    const float* __restrict__ scal, const float* __restrict__ wcolp,
    const float* __restrict__ bias,
    const float* __restrict__ c_in, float* __restrict__ c_out,
    float* __restrict__ h_out, long ldh)
{
    const int tm = tid >> 4, tn = tid & 15;
    const int gp0 = n0 + tn * 4;
    const int jh  = gp0 >> 2;
    float4 bi = *(const float4*)&bias[gp0];
    float4 wc = make_float4(0.f, 0.f, 0.f, 0.f);
    if (HASSCAL) wc = *(const float4*)&wcolp[gp0];

#pragma unroll
    for (int i = 0; i < 4; ++i) {
        int b = m0 + tm * 4 + i;
        float2 lo = unpack2(acc[i][0]);
        float2 hi = unpack2(acc[i][1]);
        float gi = lo.x + bi.x;
        float gf = lo.y + bi.y;
        float gg = hi.x + bi.z;
        float go = hi.y + bi.w;
        if (HASP) {
            float4 p = *(const float4*)(P + (long)b * ldp + gp0);
            gi += p.x; gf += p.y; gg += p.z; go += p.w;
        }
        if (HASSCAL) {
            float s = scal[b];
            gi += s * wc.x; gf += s * wc.y; gg += s * wc.z; go += s * wc.w;
        }
        float cprev = c_in[b * Hc + jh];
        float cnew  = sigf(gf) * cprev + sigf(gi) * tanhfast(gg);
        float hnew  = sigf(go) * tanhfast(cnew);
        c_out[b * Hc + jh] = cnew;
        h_out[(long)b * ldh + jh] = hnew;
    }
}

// ---------------- plain GEMM kernel: C[m,n] = sum_k A[m,k]*W[n,k] ----------------
__global__ void __launch_bounds__(256) gemm_nt(
    const float* __restrict__ A, long lda,
    const float* __restrict__ W, long ldw, int K,
    float* __restrict__ C, long ldc)
{
    __shared__ float As[32][72];
    __shared__ float Bs[32][72];
    const int tid = threadIdx.x;
    const long m0 = (long)blockIdx.x * 64;
    const int  n0 = blockIdx.y * 64;
    ull acc[4][2];
#pragma unroll
    for (int i = 0; i < 4; ++i) { acc[i][0] = 0ull; acc[i][1] = 0ull; }

    gemm_tile(A, lda, W, ldw, K, acc, As, Bs, m0, n0, tid);

    const int tm = tid >> 4, tn = tid & 15;
#pragma unroll
    for (int i = 0; i < 4; ++i) {
        float2 lo = unpack2(acc[i][0]);
        float2 hi = unpack2(acc[i][1]);
        float4 v = make_float4(lo.x, lo.y, hi.x, hi.y);
        *(float4*)(C + (m0 + tm * 4 + i) * ldc + n0 + tn * 4) = v;
    }
}

// ---------------- persistent LSTM layer: all 512 timesteps in one launch ----------------
// grid = 128 blocks: mt = bid&3 (batch tile), nt = bid>>2 (gate-column tile)
__global__ void __launch_bounds__(256) lstm_layer_persistent(
    const float* __restrict__ P,       // (B*T, G) pre-projections, row m = b*Tc+t
    const float* __restrict__ W,       // permuted Whh (G, H)
    const float* __restrict__ bias,
    const float* __restrict__ zero,
    float* __restrict__ c,             // (B, H) cell state, zero on entry
    float* __restrict__ hs)            // (B, T, H) hidden history
{
    __shared__ float As[32][72];
    __shared__ float Bs[32][72];
    const int tid = threadIdx.x, bid = blockIdx.x;
    const int m0 = (bid & 3) * 64, n0 = (bid >> 2) * 64;
    const long ldh = (long)Tc * Hc;
    const long ldp = (long)Tc * Gc;

    for (int t = 0; t < Tc; ++t) {
        const float* hin = t ? hs + (long)(t - 1) * Hc : zero;
        long lda = t ? ldh : (long)Hc;
        ull acc[4][2];
#pragma unroll
        for (int i = 0; i < 4; ++i) { acc[i][0] = 0ull; acc[i][1] = 0ull; }
        gemm_tile(hin, lda, W, (long)Hc, Hc, acc, As, Bs, (long)m0, n0, tid);
        cell_epilogue<true, false>(acc, m0, n0, tid,
                                   P + (long)t * Gc, ldp,
                                   nullptr, nullptr, bias,
                                   c, c, hs + (long)t * Hc, ldh);
        grid_sync();   // h_t fully written before any block reads it at t+1
    }
}

// ---------------- softmax + context (device fn, one batch b per block) ----------------
__device__ __forceinline__ void softmax_ctx_one(
    int b, const float* __restrict__ energy, const float* __restrict__ encout,
    float* __restrict__ ctx, float (&sm)[Tc], float (&red)[256], int tid)
{
    float e0 = energy[b * Tc + tid];
    float e1 = energy[b * Tc + tid + 256];
    red[tid] = fmaxf(e0, e1);
    __syncthreads();
    for (int s = 128; s; s >>= 1) {
        if (tid < s) red[tid] = fmaxf(red[tid], red[tid + s]);
        __syncthreads();
    }
    float m = red[0];
    __syncthreads();
    float p0 = __expf(e0 - m), p1 = __expf(e1 - m);
    sm[tid] = p0; sm[tid + 256] = p1;
    red[tid] = p0 + p1;
    __syncthreads();
    for (int s = 128; s; s >>= 1) {
        if (tid < s) red[tid] += red[tid + s];
        __syncthreads();
    }
    float inv = __fdividef(1.0f, red[0]);
    __syncthreads();
    sm[tid] *= inv; sm[tid + 256] *= inv;
    __syncthreads();

    const float* base = encout + (long)b * Tc * Hc + tid * 2;
    float2 acc = make_float2(0.f, 0.f);
#pragma unroll 4
    for (int t = 0; t < Tc; ++t) {
        float2 e = *(const float2*)(base + (long)t * Hc);
        float a = sm[t];
        acc.x += a * e.x; acc.y += a * e.y;
    }
    *(float2*)&ctx[b * Hc + tid * 2] = acc;
    __syncthreads();
}

// ---------------- persistent decoder: all 30 steps in one launch ----------------
__global__ void __launch_bounds__(256) decoder_persistent(
    const float* __restrict__ encout, const float* __restrict__ encprj,
    const float* __restrict__ c1,
    const float* __restrict__ attnW, const float* __restrict__ attnv,
    const float* __restrict__ dwrest, const float* __restrict__ dwcol,
    const float* __restrict__ dWhh0p, const float* __restrict__ dWih1p,
    const float* __restrict__ dWhh1p,
    const float* __restrict__ bD0, const float* __restrict__ bD1,
    const float* __restrict__ outW, const float* __restrict__ outb,
    float* __restrict__ hd0, float* __restrict__ hd1,
    float* __restrict__ cd0, float* __restrict__ cd1,
    float* __restrict__ h0tmp, float* __restrict__ cdump,
    float* __restrict__ ctx, float* __restrict__ decprj,
    float* __restrict__ energy, float* __restrict__ dinp,
    float* __restrict__ dout)
{
    __shared__ float As[32][72];
    __shared__ float Bs[32][72];
    __shared__ float sm[Tc];
    __shared__ float red[256];
    const int tid = threadIdx.x, bid = blockIdx.x;
    const int mt = bid & 3, nt = bid >> 2;
    const int warp = tid >> 5, lane = tid & 31;

    // init: hd0 = encout[:, T-1, :], cd0 = c1
    for (int i = bid * 256 + tid; i < Bc * Hc; i += NBLK * 256) {
        int b = i >> 9, h = i & (Hc - 1);
        hd0[i] = encout[(long)b * Tc * Hc + (long)(Tc - 1) * Hc + h];
        cd0[i] = c1[i];
    }
    grid_sync();

    float* hcur = hd0; float* ccur = cd0;
    float* hnext = hd1; float* cnext = cd1;

    for (int s = 0; s < HOR; ++s) {
        // P1: decproj = hcur @ attnW^T  (256x512: 32 tiles -> blocks 0..31)
        if (bid < 32) {
            ull acc[4][2];
#pragma unroll
            for (int i = 0; i < 4; ++i) { acc[i][0] = 0ull; acc[i][1] = 0ull; }
            int m0 = (bid & 3) * 64, n0 = (bid >> 2) * 64;
            gemm_tile(hcur, (long)Hc, attnW, (long)Hc, Hc, acc, As, Bs, (long)m0, n0, tid);
            const int tm = tid >> 4, tn = tid & 15;
#pragma unroll
            for (int i = 0; i < 4; ++i) {
                float2 lo = unpack2(acc[i][0]);
                float2 hi = unpack2(acc[i][1]);
                *(float4*)(decprj + (long)(m0 + tm * 4 + i) * Hc + n0 + tn * 4) =
                    make_float4(lo.x, lo.y, hi.x, hi.y);
            }
        }
        grid_sync();

        // P2: energies (B*T = 131072 rows; 1024 warps x 128 rows)
        {
            int row0 = bid * 1024 + warp * 128;
            for (int r = 0; r < 128; ++r) {
                int row = row0 + r;
                int b = row >> 9;
                const float* eprow = encprj + (long)row * Hc;
                const float* dprow = decprj + b * Hc;
                float part = 0.f;
#pragma unroll
                for (int i = 0; i < 16; ++i) {
                    int h = lane + 32 * i;
                    part += tanhfast(eprow[h] + dprow[h]) * attnv[h];
                }
#pragma unroll
                for (int o = 16; o; o >>= 1) part += __shfl_xor_sync(~0u, part, o);
                if (lane == 0) energy[row] = part;
            }
        }
        grid_sync();

        // P3: softmax + context, 2 batches per block
        softmax_ctx_one(bid * 2 + 0, energy, encout, ctx, sm, red, tid);
        softmax_ctx_one(bid * 2 + 1, energy, encout, ctx, sm, red, tid);
        grid_sync();

        // P4: cell1 gates = ctx@dwrest^T + hcur@dWhh0p^T + dinp*dwcol + bD0
        {
            ull acc[4][2];
#pragma unroll
            for (int i = 0; i < 4; ++i) { acc[i][0] = 0ull; acc[i][1] = 0ull; }
            int m0 = mt * 64, n0 = nt * 64;
            gemm_tile(ctx,  (long)Hc, dwrest, (long)Hc, Hc, acc, As, Bs, (long)m0, n0, tid);
            gemm_tile(hcur, (long)Hc, dWhh0p, (long)Hc, Hc, acc, As, Bs, (long)m0, n0, tid);
            cell_epilogue<false, true>(acc, m0, n0, tid,
                                       nullptr, 0, dinp, dwcol, bD0,
                                       ccur, cdump, h0tmp, (long)Hc);
        }
        grid_sync();

        // P5: cell2 gates = h0tmp@dWih1p^T + hcur@dWhh1p^T + bD1
        {
            ull acc[4][2];
#pragma unroll
            for (int i = 0; i < 4; ++i) { acc[i][0] = 0ull; acc[i][1] = 0ull; }
            int m0 = mt * 64, n0 = nt * 64;
            gemm_tile(h0tmp, (long)Hc, dWih1p, (long)Hc, Hc, acc, As, Bs, (long)m0, n0, tid);
            gemm_tile(hcur,  (long)Hc, dWhh1p, (long)Hc, Hc, acc, As, Bs, (long)m0, n0, tid);
            cell_epilogue<false, false>(acc, m0, n0, tid,
                                        nullptr, 0, nullptr, nullptr, bD1,
                                        ccur, cnext, hnext, (long)Hc);
        }
        grid_sync();

        // P6: output projection (768 warp-dots) + next dec input
        {
            int w = bid * 8 + warp;
            if (w < Bc * NQc) {
                int b = w / 3, q = w - b * 3;
                const float* hr = hnext + b * Hc;
                const float* wr = outW + q * Hc;
                float part = 0.f;
#pragma unroll
                for (int i = 0; i < 16; ++i) part += hr[lane + 32 * i] * wr[lane + 32 * i];
#pragma unroll
                for (int o = 16; o; o >>= 1) part += __shfl_xor_sync(~0u, part, o);
                if (lane == 0) {
                    float val = part + outb[q];
                    dout[(long)b * (HOR * NQc) + s * NQc + q] = val;
                    if (q == 1) dinp[b] = val;
                }
            }
        }
        grid_sync();

        // swap carry buffers
        float* th = hcur; hcur = hnext; hnext = th;
        float* tc = ccur; ccur = cnext; cnext = tc;
    }
}

// ---------------- host ----------------
static float* sym_addr(const void* symbol) {
    void* p = nullptr;
    cudaGetSymbolAddress(&p, symbol);
    return (float*)p;
}

extern "C" void kernel_launch(void* const* d_in, const int* in_sizes, int n_in,
                              void* d_out, int out_size)
{
    const float* x      = (const float*)d_in[0];
    const float* eWih0  = (const float*)d_in[1];
    const float* eWhh0  = (const float*)d_in[2];
    const float* ebih0  = (const float*)d_in[3];
    const float* ebhh0  = (const float*)d_in[4];
    const float* eWih1  = (const float*)d_in[5];
    const float* eWhh1  = (const float*)d_in[6];
    const float* ebih1  = (const float*)d_in[7];
    const float* ebhh1  = (const float*)d_in[8];
    const float* dWih0  = (const float*)d_in[9];
    const float* dWhh0  = (const float*)d_in[10];
    const float* dbih0  = (const float*)d_in[11];
    const float* dbhh0  = (const float*)d_in[12];
    const float* dWih1  = (const float*)d_in[13];
    const float* dWhh1  = (const float*)d_in[14];
    const float* dbih1  = (const float*)d_in[15];
    const float* dbhh1  = (const float*)d_in[16];
    const float* attnW  = (const float*)d_in[17];
    const float* attnv  = (const float*)d_in[18];
    const float* outW   = (const float*)d_in[19];
    const float* outb   = (const float*)d_in[20];
    float* dout = (float*)d_out;

    float* pre    = sym_addr(g_pre);
    float* hs0    = sym_addr(g_hs0);
    float* encout = sym_addr(g_encout);
    float* encprj = sym_addr(g_encproj);
    float* Wih0p  = sym_addr(g_Wih0p);
    float* Whh0p  = sym_addr(g_Whh0p);
    float* Wih1p  = sym_addr(g_Wih1p);
    float* Whh1p  = sym_addr(g_Whh1p);
    float* dwrest = sym_addr(g_dwrestp);
    float* dWhh0p = sym_addr(g_dWhh0p);
    float* dWih1p = sym_addr(g_dWih1p);
    float* dWhh1p = sym_addr(g_dWhh1p);
    float* dwcol  = sym_addr(g_dwcol0p);
    float* bE0    = sym_addr(g_bE0p);
    float* bE1    = sym_addr(g_bE1p);
    float* bD0    = sym_addr(g_bD0p);
    float* bD1    = sym_addr(g_bD1p);
    float* zero   = sym_addr(g_zero);
    float* c0     = sym_addr(g_c0);
    float* c1     = sym_addr(g_c1);
    float* hd0    = sym_addr(g_hd0);
    float* hd1    = sym_addr(g_hd1);
    float* cd0    = sym_addr(g_cd0);
    float* cd1    = sym_addr(g_cd1);
    float* cdump  = sym_addr(g_cdump);
    float* h0tmp  = sym_addr(g_h0tmp);
    float* ctx    = sym_addr(g_ctx);
    float* decprj = sym_addr(g_decproj);
    float* energy = sym_addr(g_energy);
    float* dinp   = sym_addr(g_dinp);

    // 0) prep: permutations, biases, zeros
    prep_kernel<<<(Gc * Hc + 255) / 256, 256>>>(
        x, eWih0, eWhh0, ebih0, ebhh0, eWih1, eWhh1, ebih1, ebhh1,
        dWih0, dWhh0, dbih0, dbhh0, dWih1, dWhh1, dbih1, dbhh1);

    // 1) P0 = x @ Wih0p^T  (M=131072, K=64, N=2048)
    gemm_nt<<<dim3(Bc * Tc / 64, Gc / 64), 256>>>(x, Ic, Wih0p, Ic, Ic, pre, Gc);

    // 2) layer-0 recurrence (persistent)
    lstm_layer_persistent<<<NBLK, 256>>>(pre, Whh0p, bE0, zero, c0, hs0);

    // 3) P1 = hs0 @ Wih1p^T  (hs0 (B,T,H) rows are m=b*Tc+t with lda=Hc)
    gemm_nt<<<dim3(Bc * Tc / 64, Gc / 64), 256>>>(hs0, Hc, Wih1p, Hc, Hc, pre, Gc);

    // 4) layer-1 recurrence (persistent)
    lstm_layer_persistent<<<NBLK, 256>>>(pre, Whh1p, bE1, zero, c1, encout);

    // 5) enc_proj = encout @ attn_W^T
    gemm_nt<<<dim3(Bc * Tc / 64, Hc / 64), 256>>>(encout, Hc, attnW, Hc, Hc, encprj, Hc);

    // 6) decoder, all 30 steps (persistent)
    decoder_persistent<<<NBLK, 256>>>(
        encout, encprj, c1, attnW, attnv,
        dwrest, dwcol, dWhh0p, dWih1p, dWhh1p, bD0, bD1, outW, outb,
        hd0, hd1, cd0, cd1, h0tmp, cdump, ctx, decprj, energy, dinp, dout);
}

// round 6
// speedup vs baseline: 1.7210x; 1.7210x over previous
#include <cuda_runtime.h>
#include <cuda_bf16.h>
#include <cstddef>
#include <cstdint>

typedef unsigned long long ull;

// ---------------- problem constants ----------------
constexpr int Bc  = 256;
constexpr int Tc  = 512;
constexpr int Ic  = 64;
constexpr int Hc  = 512;
constexpr int Gc  = 4 * Hc;      // 2048
constexpr int HOR = 30;
constexpr int NQc = 3;
constexpr int NBLK = 128;        // persistent grid size (<= 148 SMs -> co-resident)

// ---------------- device scratch (__device__ globals: allocation-free) ----------------
__device__ float g_pre[(size_t)Bc * Tc * Gc];                 // (B*T, 2048) pair-permuted gate pre-projections
__device__ __nv_bfloat16 g_xsplit[(size_t)Bc * Tc * 2 * Ic];  // (B*T, 128)  [hi|lo]
__device__ __nv_bfloat16 g_hs0s[(size_t)Bc * Tc * 2 * Hc];    // (B,T,1024)  layer-0 h split
__device__ __nv_bfloat16 g_enc1s[(size_t)Bc * Tc * 2 * Hc];   // (B,T,1024)  layer-1 h split
__device__ float g_encout[(size_t)Bc * Tc * Hc];              // (B,T,512)   layer-1 h fp32
__device__ float g_encproj[(size_t)Bc * Tc * Hc];             // enc_out @ attn_W^T

// encoder weights: split bf16, pair-permuted rows (n<1024: (i,f) of unit n>>1; n>=1024: (g,o))
__device__ __nv_bfloat16 g_Wih0s[Gc * 2 * Ic];
__device__ __nv_bfloat16 g_Whh0s[Gc * 2 * Hc];
__device__ __nv_bfloat16 g_Wih1s[Gc * 2 * Hc];
__device__ __nv_bfloat16 g_Whh1s[Gc * 2 * Hc];
__device__ __nv_bfloat16 g_zsplit[Bc * 2 * Hc];               // zeros
__device__ float g_bE0p2[Gc];
__device__ float g_bE1p2[Gc];

// decoder weights: fp32, old permutation gp = jh*4+q
__device__ float g_dwrestp[Gc * Hc];
__device__ float g_dWhh0p[Gc * Hc];
__device__ float g_dWih1p[Gc * Hc];
__device__ float g_dWhh1p[Gc * Hc];
__device__ float g_dwcol0p[Gc];
__device__ float g_bD0p[Gc];
__device__ float g_bD1p[Gc];

__device__ float g_c0[Bc * Hc];
__device__ float g_c1[Bc * Hc];
__device__ float g_hd0[Bc * Hc];
__device__ float g_hd1[Bc * Hc];
__device__ float g_cd0[Bc * Hc];
__device__ float g_cd1[Bc * Hc];
__device__ float g_cdump[Bc * Hc];
__device__ float g_h0tmp[Bc * Hc];
__device__ float g_ctx[Bc * Hc];
__device__ float g_decproj[Bc * Hc];
__device__ float g_energy[Bc * Tc];
__device__ float g_dinp[Bc];

// ---------------- grid barrier (monotonic release counter) ----------------
__device__ unsigned g_arrive = 0;
__device__ unsigned g_release = 0;

__device__ __forceinline__ void grid_sync() {
    __syncthreads();
    if (threadIdx.x == 0) {
        __threadfence();
        unsigned prev = *((volatile unsigned*)&g_release);
        unsigned a = atomicAdd(&g_arrive, 1u);
        if (a == gridDim.x - 1u) {
            atomicExch(&g_arrive, 0u);
            __threadfence();
            atomicExch(&g_release, prev + 1u);
        } else {
            while (*((volatile unsigned*)&g_release) == prev) __nanosleep(64);
        }
        __threadfence();
    }
    __syncthreads();
}

// ---------------- math helpers ----------------
__device__ __forceinline__ float sigf(float x) {
    return __fdividef(1.0f, 1.0f + __expf(-x));
}
__device__ __forceinline__ float tanhfast(float x) {
    return 1.0f - __fdividef(2.0f, __expf(2.0f * x) + 1.0f);
}
__device__ __forceinline__ ull pack2(float lo, float hi) {
    ull r; asm("mov.b64 %0, {%1, %2};" : "=l"(r) : "f"(lo), "f"(hi)); return r;
}
__device__ __forceinline__ float2 unpack2(ull v) {
    float2 f; asm("mov.b64 {%0, %1}, %2;" : "=f"(f.x), "=f"(f.y) : "l"(v)); return f;
}
__device__ __forceinline__ void fma2(ull& d, ull a, ull b) {
    asm("fma.rn.f32x2 %0, %1, %2, %0;" : "+l"(d) : "l"(a), "l"(b));
}

// ---------------- tensor-core helpers ----------------
__device__ __forceinline__ void ldsm_x4(uint32_t (&r)[4], uint32_t addr) {
    asm volatile("ldmatrix.sync.aligned.m8n8.x4.shared.b16 {%0,%1,%2,%3}, [%4];"
        : "=r"(r[0]), "=r"(r[1]), "=r"(r[2]), "=r"(r[3]) : "r"(addr));
}
__device__ __forceinline__ void ldsm_x2(uint32_t (&r)[2], uint32_t addr) {
    asm volatile("ldmatrix.sync.aligned.m8n8.x2.shared.b16 {%0,%1}, [%2];"
        : "=r"(r[0]), "=r"(r[1]) : "r"(addr));
}
__device__ __forceinline__ void mma16816(float (&d)[4], const uint32_t (&a)[4], const uint32_t (&b)[2]) {
    asm volatile("mma.sync.aligned.m16n8k16.row.col.f32.bf16.bf16.f32 "
        "{%0,%1,%2,%3}, {%4,%5,%6,%7}, {%8,%9}, {%0,%1,%2,%3};"
        : "+f"(d[0]), "+f"(d[1]), "+f"(d[2]), "+f"(d[3])
        : "r"(a[0]), "r"(a[1]), "r"(a[2]), "r"(a[3]), "r"(b[0]), "r"(b[1]));
}

// ---------------- split helper ----------------
__device__ __forceinline__ void bsplit(float v, __nv_bfloat16& hi, __nv_bfloat16& lo) {
    hi = __float2bfloat16_rn(v);
    lo = __float2bfloat16_rn(v - __bfloat162float(hi));
}

// ---------------- prep ----------------
__global__ void prep_kernel(const float* __restrict__ x,
    const float* __restrict__ eWih0, const float* __restrict__ eWhh0,
    const float* __restrict__ ebih0, const float* __restrict__ ebhh0,
    const float* __restrict__ eWih1, const float* __restrict__ eWhh1,
    const float* __restrict__ ebih1, const float* __restrict__ ebhh1,
    const float* __restrict__ dWih0, const float* __restrict__ dWhh0,
    const float* __restrict__ dbih0, const float* __restrict__ dbhh0,
    const float* __restrict__ dWih1, const float* __restrict__ dWhh1,
    const float* __restrict__ dbih1, const float* __restrict__ dbhh1)
{
    int idx = blockIdx.x * 256 + threadIdx.x;   // grid covers B*T*I = 8,388,608

    // x split: (B*T, 128) = [hi(64) | lo(64)]
    if (idx < Bc * Tc * Ic) {
        int m = idx >> 6, i = idx & 63;
        __nv_bfloat16 hi, lo;
        bsplit(x[idx], hi, lo);
        g_xsplit[(size_t)m * 128 + i] = hi;
        g_xsplit[(size_t)m * 128 + 64 + i] = lo;
    }

    if (idx < Gc * Hc) {
        int n = idx / Hc;           // also gp for decoder path
        int k = idx - n * Hc;

        // --- decoder: old permutation gp = jh*4+q ---
        int g_old = (n & 3) * Hc + (n >> 2);
        size_t so = (size_t)g_old * Hc + k;
        g_dWhh0p[idx] = dWhh0[so];
        g_dWih1p[idx] = dWih1[so];
        g_dWhh1p[idx] = dWhh1[so];
        g_dwrestp[idx] = dWih0[(size_t)g_old * (Hc + 1) + 1 + k];
        if (k == 0) {
            g_dwcol0p[n] = dWih0[(size_t)g_old * (Hc + 1)];
            g_bD0p[n] = dbih0[g_old] + dbhh0[g_old];
            g_bD1p[n] = dbih1[g_old] + dbhh1[g_old];
        }

        // --- encoder: pair permutation ---
        // n < 1024: unit jh = n>>1, gate = (n&1) ? f : i
        // n >= 1024: unit jh = (n-1024)>>1, gate = (n&1) ? o : g
        int q  = (n < 1024) ? (n & 1) : 2 + (n & 1);
        int jh = ((n < 1024) ? n : n - 1024) >> 1;
        int g2 = q * Hc + jh;
        size_t s2 = (size_t)g2 * Hc + k;
        __nv_bfloat16 hi, lo;
        bsplit(eWhh0[s2], hi, lo);
        g_Whh0s[(size_t)n * 1024 + k] = hi; g_Whh0s[(size_t)n * 1024 + 512 + k] = lo;
        bsplit(eWih1[s2], hi, lo);
        g_Wih1s[(size_t)n * 1024 + k] = hi; g_Wih1s[(size_t)n * 1024 + 512 + k] = lo;
        bsplit(eWhh1[s2], hi, lo);
        g_Whh1s[(size_t)n * 1024 + k] = hi; g_Whh1s[(size_t)n * 1024 + 512 + k] = lo;
        if (k < Ic) {
            bsplit(eWih0[(size_t)g2 * Ic + k], hi, lo);
            g_Wih0s[(size_t)n * 128 + k] = hi;
            g_Wih0s[(size_t)n * 128 + 64 + k] = lo;
        }
        if (k == 0) {
            g_bE0p2[n] = ebih0[g2] + ebhh0[g2];
            g_bE1p2[n] = ebih1[g2] + ebhh1[g2];
        }
    }

    if (idx < Bc * 2 * Hc) g_zsplit[idx] = __float2bfloat16_rn(0.0f);
    if (idx < Bc * Hc) { g_c0[idx] = 0.f; g_c1[idx] = 0.f; }
    if (idx < Bc) g_dinp[idx] = x[(size_t)idx * Tc * Ic + (size_t)(Tc - 1) * Ic];
}

// ---------------- HMMA block core ----------------
// Block tile: (MF*16) M-rows x (64 if-cols + 64 go-cols). 8 warps, warp w owns
// if-cols [w*8, w*8+8) and the paired go-cols. Smem rows = 64 bf16 (8 x 16B
// chunks), swizzle chunk' = chunk ^ (row & 7).
template<int MF>
__device__ __forceinline__ void hmma_core(
    const __nv_bfloat16* __restrict__ A, size_t lda,
    const __nv_bfloat16* __restrict__ Wif, const __nv_bfloat16* __restrict__ Wgo,
    size_t ldw, int kchunks,
    float (&aif)[MF][4], float (&ago)[MF][4],
    char* sA, char* sW, int tid, int wid, int lane)
{
    uint32_t sAb = (uint32_t)__cvta_generic_to_shared(sA);
    uint32_t sWb = (uint32_t)__cvta_generic_to_shared(sW);
    const int lr = lane & 15, hb = lane >> 4;
    const int nb = wid * 8 + (lane & 7), bsel = (lane >> 3) & 1;

    for (int kc = 0; kc < kchunks; ++kc) {
        __syncthreads();
#pragma unroll
        for (int j = 0; j < MF / 2; ++j) {
            int i = tid + j * 256;
            int r = i >> 3, c = i & 7;
            *(uint4*)(sA + ((r * 8 + (c ^ (r & 7))) << 4)) =
                *(const uint4*)(A + (size_t)r * lda + kc * 64 + c * 8);
        }
#pragma unroll
        for (int j = 0; j < 2; ++j) {
            int i = tid + j * 256;
            int r = i >> 3, c = i & 7;
            *(uint4*)(sW + ((r * 8 + (c ^ (r & 7))) << 4)) =
                *(const uint4*)(Wif + (size_t)r * ldw + kc * 64 + c * 8);
            *(uint4*)(sW + 8192 + ((r * 8 + (c ^ (r & 7))) << 4)) =
                *(const uint4*)(Wgo + (size_t)r * ldw + kc * 64 + c * 8);
        }
        __syncthreads();
#pragma unroll
        for (int s = 0; s < 4; ++s) {
            uint32_t b_if[2], b_go[2];
            int cb = 2 * s + bsel;
            uint32_t boff = (uint32_t)((nb * 8 + (cb ^ (nb & 7))) << 4);
            ldsm_x2(b_if, sWb + boff);
            ldsm_x2(b_go, sWb + 8192u + boff);
            int ca = 2 * s + hb;
#pragma unroll
            for (int mf = 0; mf < MF; ++mf) {
                uint32_t a[4];
                int row = mf * 16 + lr;
                ldsm_x4(a, sAb + (uint32_t)((row * 8 + (ca ^ (lr & 7))) << 4));
                mma16816(aif[mf], a, b_if);
                mma16816(ago[mf], a, b_go);
            }
        }
    }
}

// ---------------- HMMA GEMM: C(M,2048 pair-permuted) = Asplit @ Wsplit^T ----------------
__global__ void __launch_bounds__(256) gemm_hmma(
    const __nv_bfloat16* __restrict__ A, size_t lda,
    const __nv_bfloat16* __restrict__ Ws, size_t ldw, int kprime,
    float* __restrict__ C, size_t ldc)
{
    constexpr int MF = 4;
    __shared__ __align__(16) char sA[MF * 16 * 128];
    __shared__ __align__(16) char sW[128 * 128];
    const int tid = threadIdx.x, wid = tid >> 5, lane = tid & 31;
    const size_t m0 = (size_t)blockIdx.x * (MF * 16);
    const int ny = blockIdx.y;

    float aif[MF][4], ago[MF][4];
#pragma unroll
    for (int i = 0; i < MF; ++i)
#pragma unroll
        for (int j = 0; j < 4; ++j) { aif[i][j] = 0.f; ago[i][j] = 0.f; }

    hmma_core<MF>(A + m0 * lda, lda,
                  Ws + (size_t)(ny * 64) * ldw,
                  Ws + (size_t)(1024 + ny * 64) * ldw,
                  ldw, kprime / 64, aif, ago, sA, sW, tid, wid, lane);

    const int u = ny * 32 + wid * 4 + (lane & 3);
    const int r0 = lane >> 2;
#pragma unroll
    for (int mf = 0; mf < MF; ++mf) {
        size_t row = m0 + mf * 16 + r0;
        *(float2*)(C + row * ldc + 2 * u)            = make_float2(aif[mf][0], aif[mf][1]);
        *(float2*)(C + (row + 8) * ldc + 2 * u)      = make_float2(aif[mf][2], aif[mf][3]);
        *(float2*)(C + row * ldc + 1024 + 2 * u)     = make_float2(ago[mf][0], ago[mf][1]);
        *(float2*)(C + (row + 8) * ldc + 1024 + 2 * u) = make_float2(ago[mf][2], ago[mf][3]);
    }
}

// ---------------- persistent HMMA LSTM layer ----------------
// grid = 128: bm = bid>>4 (8 batch tiles of 32), ny = bid&15 (16 unit tiles of 32)
template<bool WRITEF32>
__global__ void __launch_bounds__(256) lstm_hmma(
    __nv_bfloat16* __restrict__ hsplit,          // (B,T,1024) in/out
    const __nv_bfloat16* __restrict__ zsplit,    // (B,1024) zeros
    const __nv_bfloat16* __restrict__ Ws,        // (2048,1024) split Whh
    const float* __restrict__ pre,               // (B*T,2048)
    const float* __restrict__ bias,              // (2048) pair-permuted
    float* __restrict__ c,                       // (B,512)
    float* __restrict__ hf32)                    // (B,T,512) or unused
{
    constexpr int MF = 2;
    __shared__ __align__(16) char sA[MF * 16 * 128];
    __shared__ __align__(16) char sW[128 * 128];
    const int tid = threadIdx.x, wid = tid >> 5, lane = tid & 31;
    const int bm = blockIdx.x >> 4, ny = blockIdx.x & 15;
    const int m0 = bm * 32;
    const __nv_bfloat16* Wif = Ws + (size_t)(ny * 64) * 1024;
    const __nv_bfloat16* Wgo = Ws + (size_t)(1024 + ny * 64) * 1024;

    const int u = ny * 32 + wid * 4 + (lane & 3);
    const float2 bif = *(const float2*)(bias + 2 * u);
    const float2 bgo = *(const float2*)(bias + 1024 + 2 * u);

    for (int t = 0; t < Tc; ++t) {
        const __nv_bfloat16* Ablk;
        size_t lda;
        if (t) { Ablk = hsplit + ((size_t)m0 * Tc + (t - 1)) * 1024; lda = (size_t)Tc * 1024; }
        else   { Ablk = zsplit + (size_t)m0 * 1024;                  lda = 1024; }

        float aif[MF][4], ago[MF][4];
#pragma unroll
        for (int i = 0; i < MF; ++i)
#pragma unroll
            for (int j = 0; j < 4; ++j) { aif[i][j] = 0.f; ago[i][j] = 0.f; }

        hmma_core<MF>(Ablk, lda, Wif, Wgo, 1024, 16, aif, ago, sA, sW, tid, wid, lane);

#pragma unroll
        for (int mf = 0; mf < MF; ++mf) {
#pragma unroll
            for (int half = 0; half < 2; ++half) {
                int b = m0 + mf * 16 + (lane >> 2) + half * 8;
                int i0 = half * 2;
                const float* Pr = pre + ((size_t)b * Tc + t) * 2048;
                float2 pif = *(const float2*)(Pr + 2 * u);
                float2 pgo = *(const float2*)(Pr + 1024 + 2 * u);
                float gi = aif[mf][i0]     + pif.x + bif.x;
                float gf = aif[mf][i0 + 1] + pif.y + bif.y;
                float gg = ago[mf][i0]     + pgo.x + bgo.x;
                float go = ago[mf][i0 + 1] + pgo.y + bgo.y;
                float cp = c[b * Hc + u];
                float cn = sigf(gf) * cp + sigf(gi) * tanhfast(gg);
                float h  = sigf(go) * tanhfast(cn);
                c[b * Hc + u] = cn;
                size_t hrow = (size_t)b * Tc + t;
                __nv_bfloat16 hh = __float2bfloat16_rn(h);
                hsplit[hrow * 1024 + u] = hh;
                hsplit[hrow * 1024 + 512 + u] = __float2bfloat16_rn(h - __bfloat162float(hh));
                if (WRITEF32) hf32[hrow * 512 + u] = h;
            }
        }
        grid_sync();
    }
}

// ---------------- fp32 GEMM tile core (decoder + encproj) ----------------
__device__ __forceinline__ void gemm_tile(
    const float* __restrict__ A, long lda,
    const float* __restrict__ W, long ldw, int K,
    ull (&acc)[4][2],
    float (&As)[32][72], float (&Bs)[32][72],
    long m0, int n0, int tid)
{
    const int lk = tid & 7, lm = tid >> 3;
    const float* ap = A + (m0 + lm) * lda + lk * 4;
    const float* wp = W + (long)(n0 + lm) * ldw + lk * 4;
    const int tm = tid >> 4, tn = tid & 15;

    for (int k0 = 0; k0 < K; k0 += 32) {
        float4 a0 = *(const float4*)(ap + k0);
        float4 a1 = *(const float4*)(ap + (long)32 * lda + k0);
        float4 w0 = *(const float4*)(wp + k0);
        float4 w1 = *(const float4*)(wp + (long)32 * ldw + k0);
        __syncthreads();
        As[lk*4+0][lm] = a0.x; As[lk*4+1][lm] = a0.y; As[lk*4+2][lm] = a0.z; As[lk*4+3][lm] = a0.w;
        As[lk*4+0][lm+32] = a1.x; As[lk*4+1][lm+32] = a1.y; As[lk*4+2][lm+32] = a1.z; As[lk*4+3][lm+32] = a1.w;
        Bs[lk*4+0][lm] = w0.x; Bs[lk*4+1][lm] = w0.y; Bs[lk*4+2][lm] = w0.z; Bs[lk*4+3][lm] = w0.w;
        Bs[lk*4+0][lm+32] = w1.x; Bs[lk*4+1][lm+32] = w1.y; Bs[lk*4+2][lm+32] = w1.z; Bs[lk*4+3][lm+32] = w1.w;
        __syncthreads();
#pragma unroll
        for (int k = 0; k < 32; ++k) {
            float4 av = *(const float4*)&As[k][tm * 4];
            float4 bv = *(const float4*)&Bs[k][tn * 4];
            ull bl = pack2(bv.x, bv.y);
            ull bh = pack2(bv.z, bv.w);
            ull aa;
            aa = pack2(av.x, av.x); fma2(acc[0][0], aa, bl); fma2(acc[0][1], aa, bh);
            aa = pack2(av.y, av.y); fma2(acc[1][0], aa, bl); fma2(acc[1][1], aa, bh);
            aa = pack2(av.z, av.z); fma2(acc[2][0], aa, bl); fma2(acc[2][1], aa, bh);
            aa = pack2(av.w, av.w); fma2(acc[3][0], aa, bl); fma2(acc[3][1], aa, bh);
        }
    }
}

// decoder LSTM cell epilogue (old permutation)
template <bool HASSCAL>
__device__ __forceinline__ void cell_epilogue(
    ull (&acc)[4][2], int m0, int n0, int tid,
    const float* __restrict__ scal, const float* __restrict__ wcolp,
    const float* __restrict__ bias,
    const float* __restrict__ c_in, float* __restrict__ c_out,
    float* __restrict__ h_out)
{
    const int tm = tid >> 4, tn = tid & 15;
    const int gp0 = n0 + tn * 4;
    const int jh  = gp0 >> 2;
    float4 bi = *(const float4*)&bias[gp0];
    float4 wc = make_float4(0.f, 0.f, 0.f, 0.f);
    if (HASSCAL) wc = *(const float4*)&wcolp[gp0];

#pragma unroll
    for (int i = 0; i < 4; ++i) {
        int b = m0 + tm * 4 + i;
        float2 lo = unpack2(acc[i][0]);
        float2 hi = unpack2(acc[i][1]);
        float gi = lo.x + bi.x;
        float gf = lo.y + bi.y;
        float gg = hi.x + bi.z;
        float go = hi.y + bi.w;
        if (HASSCAL) {
            float s = scal[b];
            gi += s * wc.x; gf += s * wc.y; gg += s * wc.z; go += s * wc.w;
        }
        float cprev = c_in[b * Hc + jh];
        float cnew  = sigf(gf) * cprev + sigf(gi) * tanhfast(gg);
        float hnew  = sigf(go) * tanhfast(cnew);
        c_out[b * Hc + jh] = cnew;
        h_out[(long)b * Hc + jh] = hnew;
    }
}

// plain fp32 GEMM (encproj)
__global__ void __launch_bounds__(256) gemm_nt(
    const float* __restrict__ A, long lda,
    const float* __restrict__ W, long ldw, int K,
    float* __restrict__ C, long ldc)
{
    __shared__ float As[32][72];
    __shared__ float Bs[32][72];
    const int tid = threadIdx.x;
    const long m0 = (long)blockIdx.x * 64;
    const int  n0 = blockIdx.y * 64;
    ull acc[4][2];
#pragma unroll
    for (int i = 0; i < 4; ++i) { acc[i][0] = 0ull; acc[i][1] = 0ull; }

    gemm_tile(A, lda, W, ldw, K, acc, As, Bs, m0, n0, tid);

    const int tm = tid >> 4, tn = tid & 15;
#pragma unroll
    for (int i = 0; i < 4; ++i) {
        float2 lo = unpack2(acc[i][0]);
        float2 hi = unpack2(acc[i][1]);
        *(float4*)(C + (m0 + tm * 4 + i) * ldc + n0 + tn * 4) =
            make_float4(lo.x, lo.y, hi.x, hi.y);
    }
}

// ---------------- softmax + context ----------------
__device__ __forceinline__ void softmax_ctx_one(
    int b, const float* __restrict__ energy, const float* __restrict__ encout,
    float* __restrict__ ctx, float (&sm)[Tc], float (&red)[256], int tid)
{
    float e0 = energy[b * Tc + tid];
    float e1 = energy[b * Tc + tid + 256];
    red[tid] = fmaxf(e0, e1);
    __syncthreads();
    for (int s = 128; s; s >>= 1) {
        if (tid < s) red[tid] = fmaxf(red[tid], red[tid + s]);
        __syncthreads();
    }
    float m = red[0];
    __syncthreads();
    float p0 = __expf(e0 - m), p1 = __expf(e1 - m);
    sm[tid] = p0; sm[tid + 256] = p1;
    red[tid] = p0 + p1;
    __syncthreads();
    for (int s = 128; s; s >>= 1) {
        if (tid < s) red[tid] += red[tid + s];
        __syncthreads();
    }
    float inv = __fdividef(1.0f, red[0]);
    __syncthreads();
    sm[tid] *= inv; sm[tid + 256] *= inv;
    __syncthreads();

    const float* base = encout + (long)b * Tc * Hc + tid * 2;
    float2 acc = make_float2(0.f, 0.f);
#pragma unroll 4
    for (int t = 0; t < Tc; ++t) {
        float2 e = *(const float2*)(base + (long)t * Hc);
        float a = sm[t];
        acc.x += a * e.x; acc.y += a * e.y;
    }
    *(float2*)&ctx[b * Hc + tid * 2] = acc;
    __syncthreads();
}

// ---------------- persistent decoder ----------------
__global__ void __launch_bounds__(256) decoder_persistent(
    const float* __restrict__ encout, const float* __restrict__ encprj,
    const float* __restrict__ c1,
    const float* __restrict__ attnW, const float* __restrict__ attnv,
    const float* __restrict__ dwrest, const float* __restrict__ dwcol,
    const float* __restrict__ dWhh0p, const float* __restrict__ dWih1p,
    const float* __restrict__ dWhh1p,
    const float* __restrict__ bD0, const float* __restrict__ bD1,
    const float* __restrict__ outW, const float* __restrict__ outb,
    float* __restrict__ hd0, float* __restrict__ hd1,
    float* __restrict__ cd0, float* __restrict__ cd1,
    float* __restrict__ h0tmp, float* __restrict__ cdump,
    float* __restrict__ ctx, float* __restrict__ decprj,
    float* __restrict__ energy, float* __restrict__ dinp,
    float* __restrict__ dout)
{
    __shared__ float As[32][72];
    __shared__ float Bs[32][72];
    __shared__ float sm[Tc];
    __shared__ float red[256];
    const int tid = threadIdx.x, bid = blockIdx.x;
    const int mt = bid & 3, nt = bid >> 2;
    const int warp = tid >> 5, lane = tid & 31;

    for (int i = bid * 256 + tid; i < Bc * Hc; i += NBLK * 256) {
        int b = i >> 9, h = i & (Hc - 1);
        hd0[i] = encout[(long)b * Tc * Hc + (long)(Tc - 1) * Hc + h];
        cd0[i] = c1[i];
    }
    grid_sync();

    float* hcur = hd0; float* ccur = cd0;
    float* hnext = hd1; float* cnext = cd1;

    for (int s = 0; s < HOR; ++s) {
        if (bid < 32) {
            ull acc[4][2];
#pragma unroll
            for (int i = 0; i < 4; ++i) { acc[i][0] = 0ull; acc[i][1] = 0ull; }
            int m0 = (bid & 3) * 64, n0 = (bid >> 2) * 64;
            gemm_tile(hcur, (long)Hc, attnW, (long)Hc, Hc, acc, As, Bs, (long)m0, n0, tid);
            const int tm = tid >> 4, tn = tid & 15;
#pragma unroll
            for (int i = 0; i < 4; ++i) {
                float2 lo = unpack2(acc[i][0]);
                float2 hi = unpack2(acc[i][1]);
                *(float4*)(decprj + (long)(m0 + tm * 4 + i) * Hc + n0 + tn * 4) =
                    make_float4(lo.x, lo.y, hi.x, hi.y);
            }
        }
        grid_sync();

        {
            int row0 = bid * 1024 + warp * 128;
            for (int r = 0; r < 128; ++r) {
                int row = row0 + r;
                int b = row >> 9;
                const float* eprow = encprj + (long)row * Hc;
                const float* dprow = decprj + b * Hc;
                float part = 0.f;
#pragma unroll
                for (int i = 0; i < 16; ++i) {
                    int h = lane + 32 * i;
                    part += tanhfast(eprow[h] + dprow[h]) * attnv[h];
                }
#pragma unroll
                for (int o = 16; o; o >>= 1) part += __shfl_xor_sync(~0u, part, o);
                if (lane == 0) energy[row] = part;
            }
        }
        grid_sync();

        softmax_ctx_one(bid * 2 + 0, energy, encout, ctx, sm, red, tid);
        softmax_ctx_one(bid * 2 + 1, energy, encout, ctx, sm, red, tid);
        grid_sync();

        {
            ull acc[4][2];
#pragma unroll
            for (int i = 0; i < 4; ++i) { acc[i][0] = 0ull; acc[i][1] = 0ull; }
            int m0 = mt * 64, n0 = nt * 64;
            gemm_tile(ctx,  (long)Hc, dwrest, (long)Hc, Hc, acc, As, Bs, (long)m0, n0, tid);
            gemm_tile(hcur, (long)Hc, dWhh0p, (long)Hc, Hc, acc, As, Bs, (long)m0, n0, tid);
            cell_epilogue<true>(acc, m0, n0, tid, dinp, dwcol, bD0, ccur, cdump, h0tmp);
        }
        grid_sync();

        {
            ull acc[4][2];
#pragma unroll
            for (int i = 0; i < 4; ++i) { acc[i][0] = 0ull; acc[i][1] = 0ull; }
            int m0 = mt * 64, n0 = nt * 64;
            gemm_tile(h0tmp, (long)Hc, dWih1p, (long)Hc, Hc, acc, As, Bs, (long)m0, n0, tid);
            gemm_tile(hcur,  (long)Hc, dWhh1p, (long)Hc, Hc, acc, As, Bs, (long)m0, n0, tid);
            cell_epilogue<false>(acc, m0, n0, tid, nullptr, nullptr, bD1, ccur, cnext, hnext);
        }
        grid_sync();

        {
            int w = bid * 8 + warp;
            if (w < Bc * NQc) {
                int b = w / 3, q = w - b * 3;
                const float* hr = hnext + b * Hc;
                const float* wr = outW + q * Hc;
                float part = 0.f;
#pragma unroll
                for (int i = 0; i < 16; ++i) part += hr[lane + 32 * i] * wr[lane + 32 * i];
#pragma unroll
                for (int o = 16; o; o >>= 1) part += __shfl_xor_sync(~0u, part, o);
                if (lane == 0) {
                    float val = part + outb[q];
                    dout[(long)b * (HOR * NQc) + s * NQc + q] = val;
                    if (q == 1) dinp[b] = val;
                }
            }
        }
        grid_sync();

        float* th = hcur; hcur = hnext; hnext = th;
        float* tc = ccur; ccur = cnext; cnext = tc;
    }
}

// ---------------- host ----------------
template <typename T>
static T* sym_addr(const void* symbol) {
    void* p = nullptr;
    cudaGetSymbolAddress(&p, symbol);
    return (T*)p;
}

extern "C" void kernel_launch(void* const* d_in, const int* in_sizes, int n_in,
                              void* d_out, int out_size)
{
    const float* x      = (const float*)d_in[0];
    const float* eWih0  = (const float*)d_in[1];
    const float* eWhh0  = (const float*)d_in[2];
    const float* ebih0  = (const float*)d_in[3];
    const float* ebhh0  = (const float*)d_in[4];
    const float* eWih1  = (const float*)d_in[5];
    const float* eWhh1  = (const float*)d_in[6];
    const float* ebih1  = (const float*)d_in[7];
    const float* ebhh1  = (const float*)d_in[8];
    const float* dWih0  = (const float*)d_in[9];
    const float* dWhh0  = (const float*)d_in[10];
    const float* dbih0  = (const float*)d_in[11];
    const float* dbhh0  = (const float*)d_in[12];
    const float* dWih1  = (const float*)d_in[13];
    const float* dWhh1  = (const float*)d_in[14];
    const float* dbih1  = (const float*)d_in[15];
    const float* dbhh1  = (const float*)d_in[16];
    const float* attnW  = (const float*)d_in[17];
    const float* attnv  = (const float*)d_in[18];
    const float* outW   = (const float*)d_in[19];
    const float* outb   = (const float*)d_in[20];
    float* dout = (float*)d_out;

    float* pre    = sym_addr<float>(g_pre);
    __nv_bfloat16* xsplit = sym_addr<__nv_bfloat16>(g_xsplit);
    __nv_bfloat16* hs0s   = sym_addr<__nv_bfloat16>(g_hs0s);
    __nv_bfloat16* enc1s  = sym_addr<__nv_bfloat16>(g_enc1s);
    __nv_bfloat16* zsplit = sym_addr<__nv_bfloat16>(g_zsplit);
    __nv_bfloat16* Wih0s  = sym_addr<__nv_bfloat16>(g_Wih0s);
    __nv_bfloat16* Whh0s  = sym_addr<__nv_bfloat16>(g_Whh0s);
    __nv_bfloat16* Wih1s  = sym_addr<__nv_bfloat16>(g_Wih1s);
    __nv_bfloat16* Whh1s  = sym_addr<__nv_bfloat16>(g_Whh1s);
    float* encout = sym_addr<float>(g_encout);
    float* encprj = sym_addr<float>(g_encproj);
    float* bE0    = sym_addr<float>(g_bE0p2);
    float* bE1    = sym_addr<float>(g_bE1p2);
    float* dwrest = sym_addr<float>(g_dwrestp);
    float* dWhh0p = sym_addr<float>(g_dWhh0p);
    float* dWih1p = sym_addr<float>(g_dWih1p);
    float* dWhh1p = sym_addr<float>(g_dWhh1p);
    float* dwcol  = sym_addr<float>(g_dwcol0p);
    float* bD0    = sym_addr<float>(g_bD0p);
    float* bD1    = sym_addr<float>(g_bD1p);
    float* c0     = sym_addr<float>(g_c0);
    float* c1     = sym_addr<float>(g_c1);
    float* hd0    = sym_addr<float>(g_hd0);
    float* hd1    = sym_addr<float>(g_hd1);
    float* cd0    = sym_addr<float>(g_cd0);
    float* cd1    = sym_addr<float>(g_cd1);
    float* cdump  = sym_addr<float>(g_cdump);
    float* h0tmp  = sym_addr<float>(g_h0tmp);
    float* ctx    = sym_addr<float>(g_ctx);
    float* decprj = sym_addr<float>(g_decproj);
    float* energy = sym_addr<float>(g_energy);
    float* dinp   = sym_addr<float>(g_dinp);

    // 0) prep: splits, permutations, biases, zeros
    prep_kernel<<<(Bc * Tc * Ic + 255) / 256, 256>>>(
        x, eWih0, eWhh0, ebih0, ebhh0, eWih1, eWhh1, ebih1, ebhh1,
        dWih0, dWhh0, dbih0, dbhh0, dWih1, dWhh1, dbih1, dbhh1);

    // 1) P0 = xsplit @ Wih0s^T  (M=131072, K'=128)
    gemm_hmma<<<dim3(Bc * Tc / 64, 16), 256>>>(xsplit, 128, Wih0s, 128, 128, pre, Gc);

    // 2) layer-0 recurrence (persistent HMMA)
    lstm_hmma<false><<<NBLK, 256>>>(hs0s, zsplit, Whh0s, pre, bE0, c0, nullptr);

    // 3) P1 = hs0s @ Wih1s^T  (K'=1024)
    gemm_hmma<<<dim3(Bc * Tc / 64, 16), 256>>>(hs0s, 1024, Wih1s, 1024, 1024, pre, Gc);

    // 4) layer-1 recurrence (persistent HMMA, also writes fp32 encout)
    lstm_hmma<true><<<NBLK, 256>>>(enc1s, zsplit, Whh1s, pre, bE1, c1, encout);

    // 5) enc_proj = encout @ attn_W^T  (fp32)
    gemm_nt<<<dim3(Bc * Tc / 64, Hc / 64), 256>>>(encout, Hc, attnW, Hc, Hc, encprj, Hc);

    // 6) decoder, all 30 steps (persistent fp32)
    decoder_persistent<<<NBLK, 256>>>(
        encout, encprj, c1, attnW, attnv,
        dwrest, dwcol, dWhh0p, dWih1p, dWhh1p, bD0, bD1, outW, outb,
        hd0, hd1, cd0, cd1, h0tmp, cdump, ctx, decprj, energy, dinp, dout);
}

// round 7
// speedup vs baseline: 2.7920x; 1.6223x over previous
#include <cuda_runtime.h>
#include <cuda_bf16.h>
#include <cstddef>
#include <cstdint>

typedef unsigned long long ull;

// ---------------- problem constants ----------------
constexpr int Bc  = 256;
constexpr int Tc  = 512;
constexpr int Ic  = 64;
constexpr int Hc  = 512;
constexpr int Gc  = 4 * Hc;      // 2048
constexpr int HOR = 30;
constexpr int NQc = 3;
constexpr int NBLK = 128;

// ---------------- device scratch ----------------
__device__ float g_pre[(size_t)Bc * Tc * Gc];                // (B*T,2048) pair-permuted pre-projections
__device__ __nv_bfloat16 g_xb[(size_t)Bc * Tc * Ic];         // x rounded to bf16
__device__ __nv_bfloat16 g_hb0[(size_t)Bc * Tc * Hc];        // layer-0 h history bf16 (B,T,512)
__device__ __nv_bfloat16 g_hb1[(size_t)Bc * Tc * Hc];        // layer-1 h history bf16
__device__ float g_encproj[(size_t)Bc * Tc * Hc];            // fp32 enc_out @ attn_W^T

// encoder weights bf16, pair-permuted rows (n<1024: (i,f) of unit n>>1; n>=1024: (g,o))
__device__ __nv_bfloat16 g_Wih0b[Gc * Ic];
__device__ __nv_bfloat16 g_Whh0b[Gc * Hc];
__device__ __nv_bfloat16 g_Wih1b[Gc * Hc];
__device__ __nv_bfloat16 g_Whh1b[Gc * Hc];
__device__ __nv_bfloat16 g_attnWb[Hc * Hc];                  // plain layout bf16
__device__ float g_bE0p2[Gc];
__device__ float g_bE1p2[Gc];

// decoder weights fp32, permutation gp = jh*4+q
__device__ float g_dwrestp[Gc * Hc];
__device__ float g_dWhh0p[Gc * Hc];
__device__ float g_dWih1p[Gc * Hc];
__device__ float g_dWhh1p[Gc * Hc];
__device__ float g_dwcol0p[Gc];
__device__ float g_bD0p[Gc];
__device__ float g_bD1p[Gc];

__device__ float g_c1[Bc * Hc];
__device__ float g_hd0[Bc * Hc];
__device__ float g_hd1[Bc * Hc];
__device__ float g_cd0[Bc * Hc];
__device__ float g_cd1[Bc * Hc];
__device__ float g_cdump[Bc * Hc];
__device__ float g_h0tmp[Bc * Hc];
__device__ float g_ctx[Bc * Hc];
__device__ float g_decproj[Bc * Hc];
__device__ float g_energy[Bc * Tc];
__device__ float g_dinp[Bc];

// per-group step counters (zeroed by prep each run)
__device__ unsigned g_cnt0[4];
__device__ unsigned g_cnt1[4];

// decoder global barrier (self-resetting)
__device__ unsigned g_arrive = 0;
__device__ unsigned g_release = 0;

__device__ __forceinline__ void grid_sync() {
    __syncthreads();
    if (threadIdx.x == 0) {
        __threadfence();
        unsigned prev = *((volatile unsigned*)&g_release);
        unsigned a = atomicAdd(&g_arrive, 1u);
        if (a == gridDim.x - 1u) {
            atomicExch(&g_arrive, 0u);
            __threadfence();
            atomicExch(&g_release, prev + 1u);
        } else {
            while (*((volatile unsigned*)&g_release) == prev) __nanosleep(64);
        }
        __threadfence();
    }
    __syncthreads();
}

// ---------------- math helpers ----------------
__device__ __forceinline__ float sigf(float x) {
    return __fdividef(1.0f, 1.0f + __expf(-x));
}
__device__ __forceinline__ float tanhfast(float x) {
    return 1.0f - __fdividef(2.0f, __expf(2.0f * x) + 1.0f);
}
__device__ __forceinline__ ull pack2(float lo, float hi) {
    ull r; asm("mov.b64 %0, {%1, %2};" : "=l"(r) : "f"(lo), "f"(hi)); return r;
}
__device__ __forceinline__ float2 unpack2(ull v) {
    float2 f; asm("mov.b64 {%0, %1}, %2;" : "=f"(f.x), "=f"(f.y) : "l"(v)); return f;
}
__device__ __forceinline__ void fma2(ull& d, ull a, ull b) {
    asm("fma.rn.f32x2 %0, %1, %2, %0;" : "+l"(d) : "l"(a), "l"(b));
}

// ---------------- tensor-core helpers ----------------
__device__ __forceinline__ void ldsm_x4(uint32_t (&r)[4], uint32_t addr) {
    asm volatile("ldmatrix.sync.aligned.m8n8.x4.shared.b16 {%0,%1,%2,%3}, [%4];"
        : "=r"(r[0]), "=r"(r[1]), "=r"(r[2]), "=r"(r[3]) : "r"(addr));
}
__device__ __forceinline__ void ldsm_x2(uint32_t (&r)[2], uint32_t addr) {
    asm volatile("ldmatrix.sync.aligned.m8n8.x2.shared.b16 {%0,%1}, [%2];"
        : "=r"(r[0]), "=r"(r[1]) : "r"(addr));
}
__device__ __forceinline__ void mma16816(float (&d)[4], const uint32_t (&a)[4], const uint32_t (&b)[2]) {
    asm volatile("mma.sync.aligned.m16n8k16.row.col.f32.bf16.bf16.f32 "
        "{%0,%1,%2,%3}, {%4,%5,%6,%7}, {%8,%9}, {%0,%1,%2,%3};"
        : "+f"(d[0]), "+f"(d[1]), "+f"(d[2]), "+f"(d[3])
        : "r"(a[0]), "r"(a[1]), "r"(a[2]), "r"(a[3]), "r"(b[0]), "r"(b[1]));
}

// ---------------- prep ----------------
__global__ void prep_kernel(const float* __restrict__ x,
    const float* __restrict__ eWih0, const float* __restrict__ eWhh0,
    const float* __restrict__ ebih0, const float* __restrict__ ebhh0,
    const float* __restrict__ eWih1, const float* __restrict__ eWhh1,
    const float* __restrict__ ebih1, const float* __restrict__ ebhh1,
    const float* __restrict__ dWih0, const float* __restrict__ dWhh0,
    const float* __restrict__ dbih0, const float* __restrict__ dbhh0,
    const float* __restrict__ dWih1, const float* __restrict__ dWhh1,
    const float* __restrict__ dbih1, const float* __restrict__ dbhh1,
    const float* __restrict__ attnW)
{
    int idx = blockIdx.x * 256 + threadIdx.x;   // grid covers B*T*I = 8,388,608

    if (idx < Bc * Tc * Ic) g_xb[idx] = __float2bfloat16_rn(x[idx]);

    if (idx < Gc * Hc) {
        int n = idx / Hc;
        int k = idx - n * Hc;

        // decoder: permutation gp = jh*4+q (fp32)
        int g_old = (n & 3) * Hc + (n >> 2);
        size_t so = (size_t)g_old * Hc + k;
        g_dWhh0p[idx] = dWhh0[so];
        g_dWih1p[idx] = dWih1[so];
        g_dWhh1p[idx] = dWhh1[so];
        g_dwrestp[idx] = dWih0[(size_t)g_old * (Hc + 1) + 1 + k];
        if (k == 0) {
            g_dwcol0p[n] = dWih0[(size_t)g_old * (Hc + 1)];
            g_bD0p[n] = dbih0[g_old] + dbhh0[g_old];
            g_bD1p[n] = dbih1[g_old] + dbhh1[g_old];
        }

        // encoder: pair permutation, plain bf16
        int q  = (n < 1024) ? (n & 1) : 2 + (n & 1);
        int jh = ((n < 1024) ? n : n - 1024) >> 1;
        int g2 = q * Hc + jh;
        size_t s2 = (size_t)g2 * Hc + k;
        g_Whh0b[idx] = __float2bfloat16_rn(eWhh0[s2]);
        g_Wih1b[idx] = __float2bfloat16_rn(eWih1[s2]);
        g_Whh1b[idx] = __float2bfloat16_rn(eWhh1[s2]);
        if (k < Ic) g_Wih0b[(size_t)n * Ic + k] = __float2bfloat16_rn(eWih0[(size_t)g2 * Ic + k]);
        if (k == 0) {
            g_bE0p2[n] = ebih0[g2] + ebhh0[g2];
            g_bE1p2[n] = ebih1[g2] + ebhh1[g2];
        }
    }

    if (idx < Hc * Hc) g_attnWb[idx] = __float2bfloat16_rn(attnW[idx]);
    if (idx < 4) { g_cnt0[idx] = 0u; g_cnt1[idx] = 0u; }
    if (idx < Bc) g_dinp[idx] = x[(size_t)idx * Tc * Ic + (size_t)(Tc - 1) * Ic];
}

// ---------------- HMMA streaming core (one-shot GEMMs) ----------------
// Block tile: 64 M-rows x (64 "if" cols + 64 "go" cols). 8 warps.
template<int MF>
__device__ __forceinline__ void hmma_core(
    const __nv_bfloat16* __restrict__ A, size_t lda,
    const __nv_bfloat16* __restrict__ Wif, const __nv_bfloat16* __restrict__ Wgo,
    size_t ldw, int kchunks,
    float (&aif)[MF][4], float (&ago)[MF][4],
    char* sA, char* sW, int tid, int wid, int lane)
{
    uint32_t sAb = (uint32_t)__cvta_generic_to_shared(sA);
    uint32_t sWb = (uint32_t)__cvta_generic_to_shared(sW);
    const int lr = lane & 15, hb = lane >> 4;
    const int nb = wid * 8 + (lane & 7), bsel = (lane >> 3) & 1;

    for (int kc = 0; kc < kchunks; ++kc) {
        __syncthreads();
#pragma unroll
        for (int j = 0; j < MF / 2; ++j) {
            int i = tid + j * 256;
            int r = i >> 3, c = i & 7;
            *(uint4*)(sA + ((r * 8 + (c ^ (r & 7))) << 4)) =
                *(const uint4*)(A + (size_t)r * lda + kc * 64 + c * 8);
        }
#pragma unroll
        for (int j = 0; j < 2; ++j) {
            int i = tid + j * 256;
            int r = i >> 3, c = i & 7;
            *(uint4*)(sW + ((r * 8 + (c ^ (r & 7))) << 4)) =
                *(const uint4*)(Wif + (size_t)r * ldw + kc * 64 + c * 8);
            *(uint4*)(sW + 8192 + ((r * 8 + (c ^ (r & 7))) << 4)) =
                *(const uint4*)(Wgo + (size_t)r * ldw + kc * 64 + c * 8);
        }
        __syncthreads();
#pragma unroll
        for (int s = 0; s < 4; ++s) {
            uint32_t b_if[2], b_go[2];
            int cb = 2 * s + bsel;
            uint32_t boff = (uint32_t)((nb * 8 + (cb ^ (nb & 7))) << 4);
            ldsm_x2(b_if, sWb + boff);
            ldsm_x2(b_go, sWb + 8192u + boff);
            int ca = 2 * s + hb;
#pragma unroll
            for (int mf = 0; mf < MF; ++mf) {
                uint32_t a[4];
                int row = mf * 16 + lr;
                ldsm_x4(a, sAb + (uint32_t)((row * 8 + (ca ^ (lr & 7))) << 4));
                mma16816(aif[mf], a, b_if);
                mma16816(ago[mf], a, b_go);
            }
        }
    }
}

// ---------------- one-shot bf16 GEMM ----------------
// PAIRED: C cols 2u / 1024+2u (pair-permuted gates, ldc=2048)
// !PAIRED: C cols ny*128 + local / ny*128 + 64 + local (plain)
template<bool PAIRED>
__global__ void __launch_bounds__(256) gemm_bf16(
    const __nv_bfloat16* __restrict__ A, size_t lda,
    const __nv_bfloat16* __restrict__ Ws, size_t ldw, int K,
    float* __restrict__ C, size_t ldc)
{
    constexpr int MF = 4;
    __shared__ __align__(16) char sA[MF * 16 * 128];
    __shared__ __align__(16) char sW[128 * 128];
    const int tid = threadIdx.x, wid = tid >> 5, lane = tid & 31;
    const size_t m0 = (size_t)blockIdx.x * (MF * 16);
    const int ny = blockIdx.y;

    float aif[MF][4], ago[MF][4];
#pragma unroll
    for (int i = 0; i < MF; ++i)
#pragma unroll
        for (int j = 0; j < 4; ++j) { aif[i][j] = 0.f; ago[i][j] = 0.f; }

    const __nv_bfloat16* Wif;
    const __nv_bfloat16* Wgo;
    if (PAIRED) {
        Wif = Ws + (size_t)(ny * 64) * ldw;
        Wgo = Ws + (size_t)(1024 + ny * 64) * ldw;
    } else {
        Wif = Ws + (size_t)(ny * 128) * ldw;
        Wgo = Ws + (size_t)(ny * 128 + 64) * ldw;
    }

    hmma_core<MF>(A + m0 * lda, lda, Wif, Wgo, ldw, K / 64, aif, ago, sA, sW, tid, wid, lane);

    const int local = 2 * (wid * 4 + (lane & 3));
    size_t cif, cgo;
    if (PAIRED) { cif = (size_t)ny * 64 + local; cgo = 1024 + (size_t)ny * 64 + local; }
    else        { cif = (size_t)ny * 128 + local; cgo = (size_t)ny * 128 + 64 + local; }
    const int r0 = lane >> 2;
#pragma unroll
    for (int mf = 0; mf < MF; ++mf) {
        size_t row = m0 + mf * 16 + r0;
        *(float2*)(C + row * ldc + cif)       = make_float2(aif[mf][0], aif[mf][1]);
        *(float2*)(C + (row + 8) * ldc + cif) = make_float2(aif[mf][2], aif[mf][3]);
        *(float2*)(C + row * ldc + cgo)       = make_float2(ago[mf][0], ago[mf][1]);
        *(float2*)(C + (row + 8) * ldc + cgo) = make_float2(ago[mf][2], ago[mf][3]);
    }
}

// ---------------- persistent LSTM layer, W-resident ----------------
// 128 blocks: mt = bid>>5 (4 batch tiles x 64), ut = bid&31 (32 unit tiles x 16).
// W tile (64 rows x 512) lives in smem for all 512 steps; c lives in registers.
// Sync: per-mt monotonic counters (groups are independent chains).
template<bool WRITEC>
__global__ void __launch_bounds__(256) lstm_hmma2(
    __nv_bfloat16* __restrict__ hb,            // (B,T,512) bf16 in/out
    const __nv_bfloat16* __restrict__ Whhb,    // (2048,512) pair-permuted
    const float* __restrict__ pre,             // (B*T,2048)
    const float* __restrict__ bias,            // (2048)
    unsigned* __restrict__ cnt,                // [4]
    float* __restrict__ cfin)                  // (B,512) final c or null
{
    extern __shared__ __align__(16) char smem[];
    char* sW = smem;              // 64KB: [kc 0..7][row 0..63][chunk 0..7 swizzled] * 16B
    char* sA = smem + 65536;      // 2 x 8KB double buffer
    const int tid = threadIdx.x, wid = tid >> 5, lane = tid & 31;
    const int mt = blockIdx.x >> 5, ut = blockIdx.x & 31;
    const int m0 = mt * 64;
    const int p = wid & 3, mh = wid >> 2;

    // resident W load (once)
    for (int i = tid; i < 4096; i += 256) {
        int r = i >> 6;
        int j = i & 63;
        int kc = j >> 3, c8 = j & 7;
        int grow = (r < 32) ? (ut * 32 + r) : (1024 + ut * 32 + (r - 32));
        *(uint4*)(sW + kc * 8192 + ((r * 8 + (c8 ^ (r & 7))) << 4)) =
            *(const uint4*)(Whhb + (size_t)grow * 512 + kc * 64 + c8 * 8);
    }
    const int u = ut * 16 + p * 4 + (lane & 3);
    const float2 bif = *(const float2*)(bias + 2 * u);
    const float2 bgo = *(const float2*)(bias + 1024 + 2 * u);
    float creg[4] = {0.f, 0.f, 0.f, 0.f};
    __syncthreads();

    const int r0 = tid >> 2, c80 = (tid & 3) * 2;   // A staging assignment
    const size_t ldab = (size_t)Tc * 512;
    uint32_t sWb32 = (uint32_t)__cvta_generic_to_shared(sW);
    uint32_t sAb32 = (uint32_t)__cvta_generic_to_shared(sA);

    unsigned target = 0;
    for (int t = 0; t < Tc; ++t) {
        // prefetch pre rows for this step (independent of barrier)
        float2 pif[4], pgo[4];
#pragma unroll
        for (int f = 0; f < 2; ++f)
#pragma unroll
            for (int hh = 0; hh < 2; ++hh) {
                int row = m0 + mh * 32 + f * 16 + (lane >> 2) + hh * 8;
                const float* Pr = pre + ((size_t)row * Tc + t) * 2048;
                pif[f * 2 + hh] = *(const float2*)(Pr + 2 * u);
                pgo[f * 2 + hh] = *(const float2*)(Pr + 1024 + 2 * u);
            }

        float aif[2][4], ago[2][4];
#pragma unroll
        for (int f = 0; f < 2; ++f)
#pragma unroll
            for (int j = 0; j < 4; ++j) { aif[f][j] = 0.f; ago[f][j] = 0.f; }

        if (t > 0) {
            if (tid == 0) {
                while (*(volatile unsigned*)&cnt[mt] < target) {}
                __threadfence();
            }
            __syncthreads();

            const __nv_bfloat16* Ab = hb + ((size_t)m0 * Tc + (t - 1)) * 512;
            uint4 rg0 = *(const uint4*)(Ab + (size_t)r0 * ldab + c80 * 8);
            uint4 rg1 = *(const uint4*)(Ab + (size_t)r0 * ldab + c80 * 8 + 8);
            *(uint4*)(sA + ((r0 * 8 + (c80 ^ (r0 & 7))) << 4)) = rg0;
            *(uint4*)(sA + ((r0 * 8 + ((c80 + 1) ^ (r0 & 7))) << 4)) = rg1;
            __syncthreads();

            for (int kc = 0; kc < 8; ++kc) {
                if (kc < 7) {
                    rg0 = *(const uint4*)(Ab + (size_t)r0 * ldab + (kc + 1) * 64 + c80 * 8);
                    rg1 = *(const uint4*)(Ab + (size_t)r0 * ldab + (kc + 1) * 64 + c80 * 8 + 8);
                }
                uint32_t sAcur = sAb32 + (uint32_t)((kc & 1) * 8192);
                uint32_t sWcur = sWb32 + (uint32_t)(kc * 8192);
#pragma unroll
                for (int s = 0; s < 4; ++s) {
                    uint32_t b_if[2], b_go[2];
                    int rb = p * 8 + (lane & 7);
                    int cb = 2 * s + ((lane >> 3) & 1);
                    ldsm_x2(b_if, sWcur + (uint32_t)((rb * 8 + (cb ^ (rb & 7))) << 4));
                    int rg = 32 + p * 8 + (lane & 7);
                    ldsm_x2(b_go, sWcur + (uint32_t)((rg * 8 + (cb ^ (rg & 7))) << 4));
#pragma unroll
                    for (int f = 0; f < 2; ++f) {
                        int ra = mh * 32 + f * 16 + (lane & 15);
                        int ca = 2 * s + (lane >> 4);
                        uint32_t a[4];
                        ldsm_x4(a, sAcur + (uint32_t)((ra * 8 + (ca ^ (ra & 7))) << 4));
                        mma16816(aif[f], a, b_if);
                        mma16816(ago[f], a, b_go);
                    }
                }
                if (kc < 7) {
                    *(uint4*)(sA + ((kc + 1) & 1) * 8192 + ((r0 * 8 + (c80 ^ (r0 & 7))) << 4)) = rg0;
                    *(uint4*)(sA + ((kc + 1) & 1) * 8192 + ((r0 * 8 + ((c80 + 1) ^ (r0 & 7))) << 4)) = rg1;
                }
                __syncthreads();
            }
        }

        // cell epilogue: 4 (row,unit) cells per thread, c in registers
#pragma unroll
        for (int f = 0; f < 2; ++f)
#pragma unroll
            for (int hh = 0; hh < 2; ++hh) {
                int row = m0 + mh * 32 + f * 16 + (lane >> 2) + hh * 8;
                int ci = f * 2 + hh;
                float gi = aif[f][2 * hh]     + pif[ci].x + bif.x;
                float gf = aif[f][2 * hh + 1] + pif[ci].y + bif.y;
                float gg = ago[f][2 * hh]     + pgo[ci].x + bgo.x;
                float go = ago[f][2 * hh + 1] + pgo[ci].y + bgo.y;
                creg[ci] = sigf(gf) * creg[ci] + sigf(gi) * tanhfast(gg);
                float h = sigf(go) * tanhfast(creg[ci]);
                hb[((size_t)row * Tc + t) * 512 + u] = __float2bfloat16_rn(h);
                if (WRITEC && t == Tc - 1) cfin[row * Hc + u] = creg[ci];
            }

        __threadfence();
        __syncthreads();
        if (tid == 0) atomicAdd(&cnt[mt], 1u);
        target += 32;
    }
}

// ---------------- fp32 GEMM tile core (decoder) ----------------
__device__ __forceinline__ void gemm_tile(
    const float* __restrict__ A, long lda,
    const float* __restrict__ W, long ldw, int K,
    ull (&acc)[4][2],
    float (&As)[32][72], float (&Bs)[32][72],
    long m0, int n0, int tid)
{
    const int lk = tid & 7, lm = tid >> 3;
    const float* ap = A + (m0 + lm) * lda + lk * 4;
    const float* wp = W + (long)(n0 + lm) * ldw + lk * 4;
    const int tm = tid >> 4, tn = tid & 15;

    for (int k0 = 0; k0 < K; k0 += 32) {
        float4 a0 = *(const float4*)(ap + k0);
        float4 a1 = *(const float4*)(ap + (long)32 * lda + k0);
        float4 w0 = *(const float4*)(wp + k0);
        float4 w1 = *(const float4*)(wp + (long)32 * ldw + k0);
        __syncthreads();
        As[lk*4+0][lm] = a0.x; As[lk*4+1][lm] = a0.y; As[lk*4+2][lm] = a0.z; As[lk*4+3][lm] = a0.w;
        As[lk*4+0][lm+32] = a1.x; As[lk*4+1][lm+32] = a1.y; As[lk*4+2][lm+32] = a1.z; As[lk*4+3][lm+32] = a1.w;
        Bs[lk*4+0][lm] = w0.x; Bs[lk*4+1][lm] = w0.y; Bs[lk*4+2][lm] = w0.z; Bs[lk*4+3][lm] = w0.w;
        Bs[lk*4+0][lm+32] = w1.x; Bs[lk*4+1][lm+32] = w1.y; Bs[lk*4+2][lm+32] = w1.z; Bs[lk*4+3][lm+32] = w1.w;
        __syncthreads();
#pragma unroll
        for (int k = 0; k < 32; ++k) {
            float4 av = *(const float4*)&As[k][tm * 4];
            float4 bv = *(const float4*)&Bs[k][tn * 4];
            ull bl = pack2(bv.x, bv.y);
            ull bh = pack2(bv.z, bv.w);
            ull aa;
            aa = pack2(av.x, av.x); fma2(acc[0][0], aa, bl); fma2(acc[0][1], aa, bh);
            aa = pack2(av.y, av.y); fma2(acc[1][0], aa, bl); fma2(acc[1][1], aa, bh);
            aa = pack2(av.z, av.z); fma2(acc[2][0], aa, bl); fma2(acc[2][1], aa, bh);
            aa = pack2(av.w, av.w); fma2(acc[3][0], aa, bl); fma2(acc[3][1], aa, bh);
        }
    }
}

template <bool HASSCAL>
__device__ __forceinline__ void cell_epilogue(
    ull (&acc)[4][2], int m0, int n0, int tid,
    const float* __restrict__ scal, const float* __restrict__ wcolp,
    const float* __restrict__ bias,
    const float* __restrict__ c_in, float* __restrict__ c_out,
    float* __restrict__ h_out)
{
    const int tm = tid >> 4, tn = tid & 15;
    const int gp0 = n0 + tn * 4;
    const int jh  = gp0 >> 2;
    float4 bi = *(const float4*)&bias[gp0];
    float4 wc = make_float4(0.f, 0.f, 0.f, 0.f);
    if (HASSCAL) wc = *(const float4*)&wcolp[gp0];

#pragma unroll
    for (int i = 0; i < 4; ++i) {
        int b = m0 + tm * 4 + i;
        float2 lo = unpack2(acc[i][0]);
        float2 hi = unpack2(acc[i][1]);
        float gi = lo.x + bi.x;
        float gf = lo.y + bi.y;
        float gg = hi.x + bi.z;
        float go = hi.y + bi.w;
        if (HASSCAL) {
            float s = scal[b];
            gi += s * wc.x; gf += s * wc.y; gg += s * wc.z; go += s * wc.w;
        }
        float cprev = c_in[b * Hc + jh];
        float cnew  = sigf(gf) * cprev + sigf(gi) * tanhfast(gg);
        float hnew  = sigf(go) * tanhfast(cnew);
        c_out[b * Hc + jh] = cnew;
        h_out[(long)b * Hc + jh] = hnew;
    }
}

// ---------------- softmax + context (bf16 encoder history) ----------------
__device__ __forceinline__ void softmax_ctx_one(
    int b, const float* __restrict__ energy, const __nv_bfloat16* __restrict__ hb1,
    float* __restrict__ ctx, float (&sm)[Tc], float (&red)[256], int tid)
{
    float e0 = energy[b * Tc + tid];
    float e1 = energy[b * Tc + tid + 256];
    red[tid] = fmaxf(e0, e1);
    __syncthreads();
    for (int s = 128; s; s >>= 1) {
        if (tid < s) red[tid] = fmaxf(red[tid], red[tid + s]);
        __syncthreads();
    }
    float m = red[0];
    __syncthreads();
    float p0 = __expf(e0 - m), p1 = __expf(e1 - m);
    sm[tid] = p0; sm[tid + 256] = p1;
    red[tid] = p0 + p1;
    __syncthreads();
    for (int s = 128; s; s >>= 1) {
        if (tid < s) red[tid] += red[tid + s];
        __syncthreads();
    }
    float inv = __fdividef(1.0f, red[0]);
    __syncthreads();
    sm[tid] *= inv; sm[tid + 256] *= inv;
    __syncthreads();

    const __nv_bfloat16* base = hb1 + (size_t)b * Tc * 512 + tid * 2;
    float2 acc = make_float2(0.f, 0.f);
#pragma unroll 4
    for (int t = 0; t < Tc; ++t) {
        __nv_bfloat162 e = *(const __nv_bfloat162*)(base + (size_t)t * 512);
        float2 ef = __bfloat1622float2(e);
        float a = sm[t];
        acc.x += a * ef.x; acc.y += a * ef.y;
    }
    *(float2*)&ctx[b * Hc + tid * 2] = acc;
    __syncthreads();
}

// ---------------- persistent decoder ----------------
__global__ void __launch_bounds__(256) decoder_persistent(
    const __nv_bfloat16* __restrict__ hb1, const float* __restrict__ encprj,
    const float* __restrict__ c1,
    const float* __restrict__ attnW, const float* __restrict__ attnv,
    const float* __restrict__ dwrest, const float* __restrict__ dwcol,
    const float* __restrict__ dWhh0p, const float* __restrict__ dWih1p,
    const float* __restrict__ dWhh1p,
    const float* __restrict__ bD0, const float* __restrict__ bD1,
    const float* __restrict__ outW, const float* __restrict__ outb,
    float* __restrict__ hd0, float* __restrict__ hd1,
    float* __restrict__ cd0, float* __restrict__ cd1,
    float* __restrict__ h0tmp, float* __restrict__ cdump,
    float* __restrict__ ctx, float* __restrict__ decprj,
    float* __restrict__ energy, float* __restrict__ dinp,
    float* __restrict__ dout)
{
    __shared__ float As[32][72];
    __shared__ float Bs[32][72];
    __shared__ float sm[Tc];
    __shared__ float red[256];
    const int tid = threadIdx.x, bid = blockIdx.x;
    const int mt = bid & 3, nt = bid >> 2;
    const int warp = tid >> 5, lane = tid & 31;

    for (int i = bid * 256 + tid; i < Bc * Hc; i += NBLK * 256) {
        int b = i >> 9, h = i & (Hc - 1);
        hd0[i] = __bfloat162float(hb1[((size_t)b * Tc + (Tc - 1)) * 512 + h]);
        cd0[i] = c1[i];
    }
    grid_sync();

    float* hcur = hd0; float* ccur = cd0;
    float* hnext = hd1; float* cnext = cd1;

    for (int s = 0; s < HOR; ++s) {
        if (bid < 32) {
            ull acc[4][2];
#pragma unroll
            for (int i = 0; i < 4; ++i) { acc[i][0] = 0ull; acc[i][1] = 0ull; }
            int m0 = (bid & 3) * 64, n0 = (bid >> 2) * 64;
            gemm_tile(hcur, (long)Hc, attnW, (long)Hc, Hc, acc, As, Bs, (long)m0, n0, tid);
            const int tm = tid >> 4, tn = tid & 15;
#pragma unroll
            for (int i = 0; i < 4; ++i) {
                float2 lo = unpack2(acc[i][0]);
                float2 hi = unpack2(acc[i][1]);
                *(float4*)(decprj + (long)(m0 + tm * 4 + i) * Hc + n0 + tn * 4) =
                    make_float4(lo.x, lo.y, hi.x, hi.y);
            }
        }
        grid_sync();

        {
            int row0 = bid * 1024 + warp * 128;
            for (int r = 0; r < 128; ++r) {
                int row = row0 + r;
                int b = row >> 9;
                const float* eprow = encprj + (long)row * Hc;
                const float* dprow = decprj + b * Hc;
                float part = 0.f;
#pragma unroll
                for (int i = 0; i < 16; ++i) {
                    int h = lane + 32 * i;
                    part += tanhfast(eprow[h] + dprow[h]) * attnv[h];
                }
#pragma unroll
                for (int o = 16; o; o >>= 1) part += __shfl_xor_sync(~0u, part, o);
                if (lane == 0) energy[row] = part;
            }
        }
        grid_sync();

        softmax_ctx_one(bid * 2 + 0, energy, hb1, ctx, sm, red, tid);
        softmax_ctx_one(bid * 2 + 1, energy, hb1, ctx, sm, red, tid);
        grid_sync();

        {
            ull acc[4][2];
#pragma unroll
            for (int i = 0; i < 4; ++i) { acc[i][0] = 0ull; acc[i][1] = 0ull; }
            int m0 = mt * 64, n0 = nt * 64;
            gemm_tile(ctx,  (long)Hc, dwrest, (long)Hc, Hc, acc, As, Bs, (long)m0, n0, tid);
            gemm_tile(hcur, (long)Hc, dWhh0p, (long)Hc, Hc, acc, As, Bs, (long)m0, n0, tid);
            cell_epilogue<true>(acc, m0, n0, tid, dinp, dwcol, bD0, ccur, cdump, h0tmp);
        }
        grid_sync();

        {
            ull acc[4][2];
#pragma unroll
            for (int i = 0; i < 4; ++i) { acc[i][0] = 0ull; acc[i][1] = 0ull; }
            int m0 = mt * 64, n0 = nt * 64;
            gemm_tile(h0tmp, (long)Hc, dWih1p, (long)Hc, Hc, acc, As, Bs, (long)m0, n0, tid);
            gemm_tile(hcur,  (long)Hc, dWhh1p, (long)Hc, Hc, acc, As, Bs, (long)m0, n0, tid);
            cell_epilogue<false>(acc, m0, n0, tid, nullptr, nullptr, bD1, ccur, cnext, hnext);
        }
        grid_sync();

        {
            int w = bid * 8 + warp;
            if (w < Bc * NQc) {
                int b = w / 3, q = w - b * 3;
                const float* hr = hnext + b * Hc;
                const float* wr = outW + q * Hc;
                float part = 0.f;
#pragma unroll
                for (int i = 0; i < 16; ++i) part += hr[lane + 32 * i] * wr[lane + 32 * i];
#pragma unroll
                for (int o = 16; o; o >>= 1) part += __shfl_xor_sync(~0u, part, o);
                if (lane == 0) {
                    float val = part + outb[q];
                    dout[(long)b * (HOR * NQc) + s * NQc + q] = val;
                    if (q == 1) dinp[b] = val;
                }
            }
        }
        grid_sync();

        float* th = hcur; hcur = hnext; hnext = th;
        float* tc = ccur; ccur = cnext; cnext = tc;
    }
}

// ---------------- host ----------------
template <typename T>
static T* sym_addr(const void* symbol) {
    void* p = nullptr;
    cudaGetSymbolAddress(&p, symbol);
    return (T*)p;
}

extern "C" void kernel_launch(void* const* d_in, const int* in_sizes, int n_in,
                              void* d_out, int out_size)
{
    const float* x      = (const float*)d_in[0];
    const float* eWih0  = (const float*)d_in[1];
    const float* eWhh0  = (const float*)d_in[2];
    const float* ebih0  = (const float*)d_in[3];
    const float* ebhh0  = (const float*)d_in[4];
    const float* eWih1  = (const float*)d_in[5];
    const float* eWhh1  = (const float*)d_in[6];
    const float* ebih1  = (const float*)d_in[7];
    const float* ebhh1  = (const float*)d_in[8];
    const float* dWih0  = (const float*)d_in[9];
    const float* dWhh0  = (const float*)d_in[10];
    const float* dbih0  = (const float*)d_in[11];
    const float* dbhh0  = (const float*)d_in[12];
    const float* dWih1  = (const float*)d_in[13];
    const float* dWhh1  = (const float*)d_in[14];
    const float* dbih1  = (const float*)d_in[15];
    const float* dbhh1  = (const float*)d_in[16];
    const float* attnW  = (const float*)d_in[17];
    const float* attnv  = (const float*)d_in[18];
    const float* outW   = (const float*)d_in[19];
    const float* outb   = (const float*)d_in[20];
    float* dout = (float*)d_out;

    float* pre    = sym_addr<float>(g_pre);
    __nv_bfloat16* xb    = sym_addr<__nv_bfloat16>(g_xb);
    __nv_bfloat16* hb0   = sym_addr<__nv_bfloat16>(g_hb0);
    __nv_bfloat16* hb1   = sym_addr<__nv_bfloat16>(g_hb1);
    __nv_bfloat16* Wih0b = sym_addr<__nv_bfloat16>(g_Wih0b);
    __nv_bfloat16* Whh0b = sym_addr<__nv_bfloat16>(g_Whh0b);
    __nv_bfloat16* Wih1b = sym_addr<__nv_bfloat16>(g_Wih1b);
    __nv_bfloat16* Whh1b = sym_addr<__nv_bfloat16>(g_Whh1b);
    __nv_bfloat16* attnWb = sym_addr<__nv_bfloat16>(g_attnWb);
    float* encprj = sym_addr<float>(g_encproj);
    float* bE0    = sym_addr<float>(g_bE0p2);
    float* bE1    = sym_addr<float>(g_bE1p2);
    float* dwrest = sym_addr<float>(g_dwrestp);
    float* dWhh0p = sym_addr<float>(g_dWhh0p);
    float* dWih1p = sym_addr<float>(g_dWih1p);
    float* dWhh1p = sym_addr<float>(g_dWhh1p);
    float* dwcol  = sym_addr<float>(g_dwcol0p);
    float* bD0    = sym_addr<float>(g_bD0p);
    float* bD1    = sym_addr<float>(g_bD1p);
    float* c1     = sym_addr<float>(g_c1);
    float* hd0    = sym_addr<float>(g_hd0);
    float* hd1    = sym_addr<float>(g_hd1);
    float* cd0    = sym_addr<float>(g_cd0);
    float* cd1    = sym_addr<float>(g_cd1);
    float* cdump  = sym_addr<float>(g_cdump);
    float* h0tmp  = sym_addr<float>(g_h0tmp);
    float* ctx    = sym_addr<float>(g_ctx);
    float* decprj = sym_addr<float>(g_decproj);
    float* energy = sym_addr<float>(g_energy);
    float* dinp   = sym_addr<float>(g_dinp);
    unsigned* cnt0 = sym_addr<unsigned>(g_cnt0);
    unsigned* cnt1 = sym_addr<unsigned>(g_cnt1);

    constexpr int LAYER_SMEM = 65536 + 16384;   // 80KB
    cudaFuncSetAttribute(lstm_hmma2<false>, cudaFuncAttributeMaxDynamicSharedMemorySize, LAYER_SMEM);
    cudaFuncSetAttribute(lstm_hmma2<true>,  cudaFuncAttributeMaxDynamicSharedMemorySize, LAYER_SMEM);

    // 0) prep
    prep_kernel<<<(Bc * Tc * Ic + 255) / 256, 256>>>(
        x, eWih0, eWhh0, ebih0, ebhh0, eWih1, eWhh1, ebih1, ebhh1,
        dWih0, dWhh0, dbih0, dbhh0, dWih1, dWhh1, dbih1, dbhh1, attnW);

    // 1) P0 = xb @ Wih0b^T   (K=64)
    gemm_bf16<true><<<dim3(Bc * Tc / 64, 16), 256>>>(xb, Ic, Wih0b, Ic, Ic, pre, Gc);

    // 2) layer-0 recurrence (W-resident persistent HMMA)
    lstm_hmma2<false><<<NBLK, 256, LAYER_SMEM>>>(hb0, Whh0b, pre, bE0, cnt0, nullptr);

    // 3) P1 = hb0 @ Wih1b^T  (K=512)
    gemm_bf16<true><<<dim3(Bc * Tc / 64, 16), 256>>>(hb0, Hc, Wih1b, Hc, Hc, pre, Gc);

    // 4) layer-1 recurrence (writes final c to c1)
    lstm_hmma2<true><<<NBLK, 256, LAYER_SMEM>>>(hb1, Whh1b, pre, bE1, cnt1, c1);

    // 5) enc_proj = hb1 @ attnWb^T  (bf16 in, fp32 out)
    gemm_bf16<false><<<dim3(Bc * Tc / 64, 4), 256>>>(hb1, Hc, attnWb, Hc, Hc, encprj, Hc);

    // 6) decoder, all 30 steps
    decoder_persistent<<<NBLK, 256>>>(
        hb1, encprj, c1, attnW, attnv,
        dwrest, dwcol, dWhh0p, dWih1p, dWhh1p, bD0, bD1, outW, outb,
        hd0, hd1, cd0, cd1, h0tmp, cdump, ctx, decprj, energy, dinp, dout);
}